// round 11
// baseline (speedup 1.0000x reference)
#include <cuda_runtime.h>
#include <cuda_fp16.h>
#include <math.h>
#include <stdint.h>

#define BATCH 64
#define SEQ 512
#define INPUT_DIM 512
#define HIDDEN 128
#define G3 384            // 3*HIDDEN
#define NUM_LAYERS 5
#define OUTPUT_DIM 96
#define NGRP 16           // batch groups (4 batches each)

typedef unsigned long long ull;

// ---------------- scratch (no allocs allowed) ----------------
__device__ float g_gx[BATCH * SEQ * G3];                  // layer-0 input gates
__device__ unsigned short g_y2h[NUM_LAYERS - 1][BATCH][SEQ][256]; // hi[128]|lo[128] fp16 transport
__device__ int g_prog[NUM_LAYERS][NGRP];                  // per (layer, group) progress
__device__ float g_hfinal[BATCH][HIDDEN];                 // last layer, last timestep

// ---------------- helpers ----------------
__device__ __forceinline__ ull pk2(float a, float b) {
    ull r; asm("mov.b64 %0, {%1, %2};" : "=l"(r) : "f"(a), "f"(b)); return r;
}
__device__ __forceinline__ void upk2(ull v, float& a, float& b) {
    asm("mov.b64 {%0, %1}, %2;" : "=f"(a), "=f"(b) : "l"(v));
}
__device__ __forceinline__ ull ffma2(ull a, ull b, ull c) {
    ull d; asm("fma.rn.f32x2 %0, %1, %2, %3;" : "=l"(d) : "l"(a), "l"(b), "l"(c)); return d;
}
__device__ __forceinline__ float sigm_fast(float x) {
    float e = __expf(-x);
    return __fdividef(1.0f, 1.0f + e);
}
__device__ __forceinline__ float tanh_fast(float x) {
    float e = __expf(-2.0f * x);
    return 1.0f - __fdividef(2.0f * e, 1.0f + e);
}
__device__ __forceinline__ uint32_t packh2(float a, float b) {
    __half2 h = __floats2half2_rn(a, b);
    return *(uint32_t*)&h;
}
__device__ __forceinline__ int ld_acquire(const int* p) {
    int v;
    asm volatile("ld.acquire.gpu.global.b32 %0, [%1];" : "=r"(v) : "l"(p) : "memory");
    return v;
}
__device__ __forceinline__ void st_release(int* p, int v) {
    asm volatile("st.release.gpu.global.b32 [%0], %1;" :: "l"(p), "r"(v) : "memory");
}
__device__ __forceinline__ uint32_t ldcg_u32(const uint32_t* p) {
    uint32_t v;
    asm volatile("ld.global.cg.u32 %0, [%1];" : "=r"(v) : "l"(p));
    return v;
}

// mma.sync m16n8k16 row.col f32.f16.f16.f32
__device__ __forceinline__ void mma16816(float d[4], const uint32_t a[4],
                                         uint32_t b0, uint32_t b1,
                                         const float c[4]) {
    asm volatile(
        "mma.sync.aligned.m16n8k16.row.col.f32.f16.f16.f32 "
        "{%0,%1,%2,%3}, {%4,%5,%6,%7}, {%8,%9}, {%10,%11,%12,%13};\n"
        : "=f"(d[0]), "=f"(d[1]), "=f"(d[2]), "=f"(d[3])
        : "r"(a[0]), "r"(a[1]), "r"(a[2]), "r"(a[3]),
          "r"(b0), "r"(b1),
          "f"(c[0]), "f"(c[1]), "f"(c[2]), "f"(c[3]));
}

// ---------------- GEMM (layer 0 only): C[M x 384] = A[M x 512]*W^T + b ----------------
__global__ __launch_bounds__(256) void gemm_nt_kernel(
    const float* __restrict__ A, const float* __restrict__ W,
    const float* __restrict__ bias, float* __restrict__ C,
    int M, int K)
{
    __shared__ __align__(16) float Ast[16][64];
    __shared__ __align__(16) float Bst[16][64];

    const int tid = threadIdx.x;
    const int m0 = blockIdx.y * 64;
    const int n0 = blockIdx.x * 64;
    const int lrow = tid >> 2;
    const int lkc  = (tid & 3) << 2;
    const float* Ap = A + (size_t)(m0 + lrow) * K + lkc;
    const float* Wp = W + (size_t)(n0 + lrow) * K + lkc;
    const int tx = tid & 15;
    const int ty = tid >> 4;

    ull acc[4][2];
#pragma unroll
    for (int i = 0; i < 4; i++) { acc[i][0] = pk2(0.f, 0.f); acc[i][1] = pk2(0.f, 0.f); }

    float4 av = *(const float4*)(Ap);
    float4 bv = *(const float4*)(Wp);

    for (int kt = 0; kt < K; kt += 16) {
        __syncthreads();
        Ast[lkc + 0][lrow] = av.x; Ast[lkc + 1][lrow] = av.y;
        Ast[lkc + 2][lrow] = av.z; Ast[lkc + 3][lrow] = av.w;
        Bst[lkc + 0][lrow] = bv.x; Bst[lkc + 1][lrow] = bv.y;
        Bst[lkc + 2][lrow] = bv.z; Bst[lkc + 3][lrow] = bv.w;
        __syncthreads();
        if (kt + 16 < K) {
            av = *(const float4*)(Ap + kt + 16);
            bv = *(const float4*)(Wp + kt + 16);
        }
#pragma unroll
        for (int k = 0; k < 16; k++) {
            float4 a4 = *(const float4*)&Ast[k][ty << 2];
            ulonglong2 b2 = *(const ulonglong2*)&Bst[k][tx << 2];
            ull pa;
            pa = pk2(a4.x, a4.x);
            acc[0][0] = ffma2(pa, b2.x, acc[0][0]); acc[0][1] = ffma2(pa, b2.y, acc[0][1]);
            pa = pk2(a4.y, a4.y);
            acc[1][0] = ffma2(pa, b2.x, acc[1][0]); acc[1][1] = ffma2(pa, b2.y, acc[1][1]);
            pa = pk2(a4.z, a4.z);
            acc[2][0] = ffma2(pa, b2.x, acc[2][0]); acc[2][1] = ffma2(pa, b2.y, acc[2][1]);
            pa = pk2(a4.w, a4.w);
            acc[3][0] = ffma2(pa, b2.x, acc[3][0]); acc[3][1] = ffma2(pa, b2.y, acc[3][1]);
        }
    }
#pragma unroll
    for (int i = 0; i < 4; i++) {
        int m = m0 + (ty << 2) + i;
        float c0, c1, c2, c3;
        upk2(acc[i][0], c0, c1);
        upk2(acc[i][1], c2, c3);
        int n = n0 + (tx << 2);
        float* Cp = C + (size_t)m * G3 + n;
        Cp[0] = c0 + bias[n + 0];
        Cp[1] = c1 + bias[n + 1];
        Cp[2] = c2 + bias[n + 2];
        Cp[3] = c3 + bias[n + 3];
    }
}

// ---------------- wavefront GRU: all 5 layers concurrent ----------------
// grid = 80 CTAs: layer l = bx>>4, group grp = bx&15 (batches 4*grp..4*grp+3).
// 256 threads = 8 warps; warp w owns hidden units [16w,16w+16) (3 gate tiles).
// m16n8k16 B columns: col 2b = fp16_hi, col 2b+1 = fp16_lo of batch b.
// Lane (g=lane>>2, tg=lane&3): batch tg, units u0=16w+g, u1=u0+8; gh = c0+c1.
// Layers>0 fuse W_ih: r/z accumulate h- and y-parts; n keeps them split.
// Cross-layer sync: release/acquire on g_prog, y via g_y2h (hi/lo fp16).
//
// dyn smem: [0, 98304)  W_ih fragment spill (uint4 per (warp,gate,kt,lane))
//           [98304, +2*8*68*4) hbuf double buffer (u32 pairs, stride 68 pads banks)
#define SMEM_WIH   0
#define SMEM_HBUF  98304
#define HB_STRIDE  68
#define SMEM_TOTAL (98304 + 2 * 8 * HB_STRIDE * 4)

__global__ void __launch_bounds__(256, 1) gru_wave(
    const float* __restrict__ w_hh_all,   // [5][384][128]
    const float* __restrict__ w_ihrest,   // [4][384][128]
    const float* __restrict__ b_ih_all,   // [5][384]
    const float* __restrict__ b_hh_all)   // [5][384]
{
    extern __shared__ char dsm[];
    uint4* wih = (uint4*)(dsm + SMEM_WIH);
    uint32_t* hball = (uint32_t*)(dsm + SMEM_HBUF);

    const int l   = blockIdx.x >> 4;
    const int grp = blockIdx.x & 15;
    const int tid = threadIdx.x;
    const int wid = tid >> 5;
    const int lane = tid & 31;
    const int g  = lane >> 2;
    const int tg = lane & 3;
    const int u0 = wid * 16 + g;
    const int u1 = u0 + 8;
    const int bat = 4 * grp + tg;          // this lane's batch (gate math)
    const int colc = lane >> 2;            // b-frag column 0..7
    const bool has_y = (l > 0);
    const bool has_cons = (l < NUM_LAYERS - 1);

    const float* w_hh = w_hh_all + (size_t)l * G3 * HIDDEN;
    const float* b_hh = b_hh_all + (size_t)l * G3;
    const float* b_ih = b_ih_all + (size_t)l * G3;

    // ---- W_hh fragments into registers ----
    uint32_t afr[3][8][4];
#pragma unroll
    for (int i = 0; i < 3; i++) {
        const int mbase = i * HIDDEN + wid * 16;
        const float* r0p = w_hh + (size_t)(mbase + g) * HIDDEN;
        const float* r1p = w_hh + (size_t)(mbase + 8 + g) * HIDDEN;
#pragma unroll
        for (int kt = 0; kt < 8; kt++) {
            const int c0 = kt * 16 + 2 * tg;
            float2 v00 = *(const float2*)(r0p + c0);
            float2 v10 = *(const float2*)(r1p + c0);
            float2 v01 = *(const float2*)(r0p + c0 + 8);
            float2 v11 = *(const float2*)(r1p + c0 + 8);
            afr[i][kt][0] = packh2(v00.x, v00.y);
            afr[i][kt][1] = packh2(v10.x, v10.y);
            afr[i][kt][2] = packh2(v01.x, v01.y);
            afr[i][kt][3] = packh2(v11.x, v11.y);
        }
    }

    // ---- W_ih fragments -> per-thread smem spill (layers > 0) ----
    if (has_y) {
        const float* wihp = w_ihrest + (size_t)(l - 1) * G3 * HIDDEN;
#pragma unroll
        for (int i = 0; i < 3; i++) {
            const int mbase = i * HIDDEN + wid * 16;
            const float* r0p = wihp + (size_t)(mbase + g) * HIDDEN;
            const float* r1p = wihp + (size_t)(mbase + 8 + g) * HIDDEN;
#pragma unroll
            for (int kt = 0; kt < 8; kt++) {
                const int c0 = kt * 16 + 2 * tg;
                float2 v00 = *(const float2*)(r0p + c0);
                float2 v10 = *(const float2*)(r1p + c0);
                float2 v01 = *(const float2*)(r0p + c0 + 8);
                float2 v11 = *(const float2*)(r1p + c0 + 8);
                uint4 f;
                f.x = packh2(v00.x, v00.y);
                f.y = packh2(v10.x, v10.y);
                f.z = packh2(v01.x, v01.y);
                f.w = packh2(v11.x, v11.y);
                wih[((wid * 3 + i) * 8 + kt) * 32 + lane] = f;
            }
        }
    }

    // ---- biases ----
    float br, bz, bin, bhn;
    if (has_y) {
        br  = b_ih[u0 % HIDDEN == u0 ? u0 : u0] + b_hh[u0];  // (kept simple below)
    }
    // (compute cleanly for both units)
    float br0, bz0, bin0, bhn0, br1, bz1, bin1, bhn1;
    if (has_y) {
        br0 = b_ih[u0] + b_hh[u0];               br1 = b_ih[u1] + b_hh[u1];
        bz0 = b_ih[u0 + HIDDEN] + b_hh[u0 + HIDDEN];
        bz1 = b_ih[u1 + HIDDEN] + b_hh[u1 + HIDDEN];
        bin0 = b_ih[u0 + 2 * HIDDEN];            bin1 = b_ih[u1 + 2 * HIDDEN];
    } else {
        br0 = b_hh[u0];                          br1 = b_hh[u1];
        bz0 = b_hh[u0 + HIDDEN];                 bz1 = b_hh[u1 + HIDDEN];
        bin0 = 0.f;                              bin1 = 0.f;
    }
    bhn0 = b_hh[u0 + 2 * HIDDEN];                bhn1 = b_hh[u1 + 2 * HIDDEN];
    (void)br; (void)bz; (void)bin; (void)bhn;

    // ---- zero hbuf (both buffers) ----
    for (int i = tid; i < 2 * 8 * HB_STRIDE; i += 256) hball[i] = 0u;

    // ---- input prefetch state ----
    const int ybatch = 4 * grp + (colc >> 1);   // batch whose vector this lane carries
    const int yhl = colc & 1;                   // 0 = hi stream, 1 = lo stream
    const float* gxb = g_gx + (size_t)bat * SEQ * G3;
    int* prog_prev = has_y ? &g_prog[l - 1][grp] : (int*)0;

    float xr0 = 0.f, xz0 = 0.f, xn0 = 0.f, xr1 = 0.f, xz1 = 0.f, xn1 = 0.f;
    uint32_t yc0[8], yc1[8];
#pragma unroll
    for (int k = 0; k < 8; k++) { yc0[k] = 0u; yc1[k] = 0u; }

    if (!has_y) {
        xr0 = __ldg(gxb + u0);            xr1 = __ldg(gxb + u1);
        xz0 = __ldg(gxb + u0 + HIDDEN);   xz1 = __ldg(gxb + u1 + HIDDEN);
        xn0 = __ldg(gxb + u0 + 2*HIDDEN); xn1 = __ldg(gxb + u1 + 2*HIDDEN);
    } else {
        while (ld_acquire(prog_prev) < 1) __nanosleep(32);
        const uint32_t* src = (const uint32_t*)&g_y2h[l - 1][ybatch][0][yhl * 128];
#pragma unroll
        for (int k = 0; k < 8; k++) {
            yc0[k] = ldcg_u32(src + k * 8 + tg);
            yc1[k] = ldcg_u32(src + k * 8 + 4 + tg);
        }
    }
    float h0 = 0.f, h1 = 0.f;
    __syncthreads();

    for (int t = 0; t < SEQ; t++) {
        // ---- prefetch next step's input ----
        float nxr0 = 0.f, nxz0 = 0.f, nxn0 = 0.f, nxr1 = 0.f, nxz1 = 0.f, nxn1 = 0.f;
        uint32_t yn0[8], yn1[8];
#pragma unroll
        for (int k = 0; k < 8; k++) { yn0[k] = 0u; yn1[k] = 0u; }
        if (t + 1 < SEQ) {
            if (!has_y) {
                const float* g1 = gxb + (size_t)(t + 1) * G3;
                nxr0 = __ldg(g1 + u0);            nxr1 = __ldg(g1 + u1);
                nxz0 = __ldg(g1 + u0 + HIDDEN);   nxz1 = __ldg(g1 + u1 + HIDDEN);
                nxn0 = __ldg(g1 + u0 + 2*HIDDEN); nxn1 = __ldg(g1 + u1 + 2*HIDDEN);
            } else {
                while (ld_acquire(prog_prev) < t + 2) __nanosleep(32);
                const uint32_t* src = (const uint32_t*)&g_y2h[l - 1][ybatch][t + 1][yhl * 128];
#pragma unroll
                for (int k = 0; k < 8; k++) {
                    yn0[k] = ldcg_u32(src + k * 8 + tg);
                    yn1[k] = ldcg_u32(src + k * 8 + 4 + tg);
                }
            }
        }

        // ---- build h B-fragments from hbuf[t&1] ----
        const uint32_t* hb = hball + (t & 1) * 8 * HB_STRIDE + colc * HB_STRIDE;
        uint32_t bh0[8], bh1[8];
#pragma unroll
        for (int k = 0; k < 8; k++) {
            bh0[k] = hb[k * 8 + tg];
            bh1[k] = hb[k * 8 + 4 + tg];
        }

        // ---- mma: 3 gates; h-part chain + y-part chain ----
        float ghh[3][2], ghy[3][2];
#pragma unroll
        for (int i = 0; i < 3; i++) {
            float da[4] = {0.f, 0.f, 0.f, 0.f};
            float db[4] = {0.f, 0.f, 0.f, 0.f};
#pragma unroll
            for (int kt = 0; kt < 8; kt++)
                mma16816(da, afr[i][kt], bh0[kt], bh1[kt], da);
            if (has_y) {
#pragma unroll
                for (int kt = 0; kt < 8; kt++) {
                    uint4 wf = wih[((wid * 3 + i) * 8 + kt) * 32 + lane];
                    uint32_t aw[4] = {wf.x, wf.y, wf.z, wf.w};
                    mma16816(db, aw, yc0[kt], yc1[kt], db);
                }
            }
            ghh[i][0] = da[0] + da[1];  ghh[i][1] = da[2] + da[3];
            ghy[i][0] = db[0] + db[1];  ghy[i][1] = db[2] + db[3];
        }

        // ---- gates (all 32 lanes; batch tg, units u0/u1) ----
        float r0g = sigm_fast(xr0 + ghh[0][0] + ghy[0][0] + br0);
        float r1g = sigm_fast(xr1 + ghh[0][1] + ghy[0][1] + br1);
        float z0g = sigm_fast(xz0 + ghh[1][0] + ghy[1][0] + bz0);
        float z1g = sigm_fast(xz1 + ghh[1][1] + ghy[1][1] + bz1);
        float n0g = tanh_fast(xn0 + ghy[2][0] + bin0 + r0g * (ghh[2][0] + bhn0));
        float n1g = tanh_fast(xn1 + ghy[2][1] + bin1 + r1g * (ghh[2][1] + bhn1));
        float hn0 = (1.0f - z0g) * n0g + z0g * h0;
        float hn1 = (1.0f - z1g) * n1g + z1g * h1;
        h0 = hn0; h1 = hn1;

        __half hi0 = __float2half_rn(hn0);
        __half hi1 = __float2half_rn(hn1);
        __half lo0 = __float2half_rn(hn0 - __half2float(hi0));
        __half lo1 = __float2half_rn(hn1 - __half2float(hi1));

        // ---- store h into next hbuf (cols 2tg hi, 2tg+1 lo) ----
        __half* hbn = (__half*)(hball + ((t + 1) & 1) * 8 * HB_STRIDE);
        hbn[(2 * tg) * (2 * HB_STRIDE) + u0] = hi0;
        hbn[(2 * tg) * (2 * HB_STRIDE) + u1] = hi1;
        hbn[(2 * tg + 1) * (2 * HB_STRIDE) + u0] = lo0;
        hbn[(2 * tg + 1) * (2 * HB_STRIDE) + u1] = lo1;

        // ---- publish y to consumer layer ----
        if (has_cons) {
            unsigned short* yd = &g_y2h[l][bat][t][0];
            yd[u0] = __half_as_ushort(hi0);
            yd[u1] = __half_as_ushort(hi1);
            yd[128 + u0] = __half_as_ushort(lo0);
            yd[128 + u1] = __half_as_ushort(lo1);
            __threadfence();
        } else if (t == SEQ - 1) {
            g_hfinal[bat][u0] = hn0;
            g_hfinal[bat][u1] = hn1;
        }
        __syncthreads();
        if (has_cons && tid == 0) st_release(&g_prog[l][grp], t + 1);

        // rotate prefetch buffers
        xr0 = nxr0; xz0 = nxz0; xn0 = nxn0;
        xr1 = nxr1; xz1 = nxz1; xn1 = nxn1;
#pragma unroll
        for (int k = 0; k < 8; k++) { yc0[k] = yn0[k]; yc1[k] = yn1[k]; }
    }
}

// ---------------- final FC ----------------
__global__ void fc_kernel(const float* __restrict__ hfinal,
                          const float* __restrict__ fc_w,
                          const float* __restrict__ fc_b,
                          float* __restrict__ out)
{
    const int b = blockIdx.x;
    const int o = threadIdx.x;   // 0..95
    const float* h = hfinal + (size_t)b * HIDDEN;
    const float* w = fc_w + (size_t)o * HIDDEN;
    float acc = fc_b[o];
#pragma unroll 16
    for (int k = 0; k < HIDDEN; k++) acc = fmaf(h[k], w[k], acc);
    out[b * OUTPUT_DIM + o] = acc;
}

// ---------------- host launch ----------------
extern "C" void kernel_launch(void* const* d_in, const int* in_sizes, int n_in,
                              void* d_out, int out_size)
{
    const float* x        = (const float*)d_in[0];
    const float* w_ih0    = (const float*)d_in[1];
    const float* w_ihrest = (const float*)d_in[2];
    const float* w_hh     = (const float*)d_in[3];
    const float* b_ih     = (const float*)d_in[4];
    const float* b_hh     = (const float*)d_in[5];
    const float* fc_w     = (const float*)d_in[6];
    const float* fc_b     = (const float*)d_in[7];
    float* out = (float*)d_out;

    float *gx, *hfin;
    int* prog;
    cudaGetSymbolAddress((void**)&gx, g_gx);
    cudaGetSymbolAddress((void**)&hfin, g_hfinal);
    cudaGetSymbolAddress((void**)&prog, g_prog);

    cudaFuncSetAttribute(gru_wave, cudaFuncAttributeMaxDynamicSharedMemorySize, SMEM_TOTAL);

    // reset progress counters (graph-capturable memset node)
    cudaMemsetAsync(prog, 0, sizeof(int) * NUM_LAYERS * NGRP);

    const int M = BATCH * SEQ;
    dim3 ggrid(G3 / 64, M / 64);
    gemm_nt_kernel<<<ggrid, 256>>>(x, w_ih0, b_ih, gx, M, INPUT_DIM);

    gru_wave<<<NUM_LAYERS * NGRP, 256, SMEM_TOTAL>>>(w_hh, w_ihrest, b_ih, b_hh);

    fc_kernel<<<BATCH, OUTPUT_DIM>>>(hfin, fc_w, fc_b, out);
}